// round 3
// baseline (speedup 1.0000x reference)
#include <cuda_runtime.h>
#include <cuda_bf16.h>
#include <math_constants.h>

#define NV 8192
#define NF 16384
#define NP 16384
#define NSPLIT 16
#define TILE 256
#define FPS (NF / NSPLIT)   // 1024 triangles per split
#define PPT 2               // points per thread
#define TPB 256

// Packed per-triangle data: ax,ay,az, bx,by,bz, cx,cy,cz, nx,ny,nz
__device__ __align__(16) float g_tri[NF * 12];
// Partial results per (split, point): {dist2, sign_dot}
__device__ float2 g_partial[NSPLIT * NP];

// Strict IEEE helpers (never FMA-contracted). Left-to-right 3-elem dot.
__device__ __forceinline__ float dot3(float x0, float x1, float x2,
                                      float y0, float y1, float y2) {
    return __fadd_rn(__fadd_rn(__fmul_rn(x0, y0), __fmul_rn(x1, y1)),
                     __fmul_rn(x2, y2));
}

__global__ void precompute_tris(const float* __restrict__ vertices,
                                const int* __restrict__ faces) {
    int f = blockIdx.x * blockDim.x + threadIdx.x;
    if (f >= NF) return;
    int i0 = faces[f * 3 + 0];
    int i1 = faces[f * 3 + 1];
    int i2 = faces[f * 3 + 2];
    float ax = vertices[i0 * 3 + 0], ay = vertices[i0 * 3 + 1], az = vertices[i0 * 3 + 2];
    float bx = vertices[i1 * 3 + 0], by = vertices[i1 * 3 + 1], bz = vertices[i1 * 3 + 2];
    float cx = vertices[i2 * 3 + 0], cy = vertices[i2 * 3 + 1], cz = vertices[i2 * 3 + 2];
    float abx = __fsub_rn(bx, ax), aby = __fsub_rn(by, ay), abz = __fsub_rn(bz, az);
    float acx = __fsub_rn(cx, ax), acy = __fsub_rn(cy, ay), acz = __fsub_rn(cz, az);
    float nx = __fsub_rn(__fmul_rn(aby, acz), __fmul_rn(abz, acy));
    float ny = __fsub_rn(__fmul_rn(abz, acx), __fmul_rn(abx, acz));
    float nz = __fsub_rn(__fmul_rn(abx, acy), __fmul_rn(aby, acx));
    float* t = &g_tri[f * 12];
    t[0] = ax; t[1] = ay; t[2] = az;
    t[3] = bx; t[4] = by; t[5] = bz;
    t[6] = cx; t[7] = cy; t[8] = cz;
    t[9] = nx; t[10] = ny; t[11] = nz;
}

// Per-point state against one triangle. The region cascade's conditions need
// no divisions; we select the region first and then issue exactly the TWO
// divisions the reference would have used for that region (trivial regions use
// 0/1 and 1/1, which are exact). Selected divisions are bit-identical to the
// reference's, so dist2 is bit-stable and the argmin never flips.
__device__ __forceinline__ void eval_point(
    float px, float py, float pz,
    float ax, float ay, float az,
    float bx, float by, float bz,
    float cx, float cy, float cz,
    float nx, float ny, float nz,
    float abx, float aby, float abz,
    float acx, float acy, float acz,
    float& best, float& sd)
{
    float apx = __fsub_rn(px, ax), apy = __fsub_rn(py, ay), apz = __fsub_rn(pz, az);
    float bpx = __fsub_rn(px, bx), bpy = __fsub_rn(py, by), bpz = __fsub_rn(pz, bz);
    float cpx = __fsub_rn(px, cx), cpy = __fsub_rn(py, cy), cpz = __fsub_rn(pz, cz);

    float d1 = dot3(abx, aby, abz, apx, apy, apz);
    float d2 = dot3(acx, acy, acz, apx, apy, apz);
    float d3 = dot3(abx, aby, abz, bpx, bpy, bpz);
    float d4 = dot3(acx, acy, acz, bpx, bpy, bpz);
    float d5 = dot3(abx, aby, abz, cpx, cpy, cpz);
    float d6 = dot3(acx, acy, acz, cpx, cpy, cpz);

    float va = __fsub_rn(__fmul_rn(d3, d6), __fmul_rn(d5, d4));
    float vb = __fsub_rn(__fmul_rn(d5, d2), __fmul_rn(d1, d6));
    float vc = __fsub_rn(__fmul_rn(d1, d4), __fmul_rn(d3, d2));
    float denom = __fadd_rn(__fadd_rn(va, vb), vc);

    float e43 = __fsub_rn(d4, d3);
    float e56 = __fsub_rn(d5, d6);

    bool c_bc = (va <= 0.0f) && (e43 >= 0.0f) && (e56 >= 0.0f);
    bool c_ac = (vb <= 0.0f) && (d2 >= 0.0f) && (d6 <= 0.0f);
    bool c_ab = (vc <= 0.0f) && (d1 >= 0.0f) && (d3 <= 0.0f);
    bool c_c  = (d6 >= 0.0f) && (d5 <= d6);
    bool c_b  = (d3 >= 0.0f) && (d4 <= d3);
    bool c_a  = (d1 <= 0.0f) && (d2 <= 0.0f);

    // Default: interior. Later assignments override (reference order).
    float nv = vb, dv = denom, nw = vc, dw = denom;
    bool bc = false;
    if (c_bc) { nv = 0.0f; dv = 1.0f; nw = e43; dw = __fadd_rn(e43, e56); bc = true; }
    if (c_ac) { nv = 0.0f; dv = 1.0f; nw = d2;  dw = __fsub_rn(d2, d6);   bc = false; }
    if (c_ab) { nv = d1;  dv = __fsub_rn(d1, d3); nw = 0.0f; dw = 1.0f;   bc = false; }
    if (c_c)  { nv = 0.0f; dv = 1.0f; nw = 1.0f; dw = 1.0f;               bc = false; }
    if (c_b)  { nv = 1.0f; dv = 1.0f; nw = 0.0f; dw = 1.0f;               bc = false; }
    if (c_a)  { nv = 0.0f; dv = 1.0f; nw = 0.0f; dw = 1.0f;               bc = false; }

    float v = __fdiv_rn(nv, (dv == 0.0f) ? 1.0f : dv);
    float w = __fdiv_rn(nw, (dw == 0.0f) ? 1.0f : dw);
    if (bc) v = __fsub_rn(1.0f, w);

    float clx = __fadd_rn(__fadd_rn(ax, __fmul_rn(v, abx)), __fmul_rn(w, acx));
    float cly = __fadd_rn(__fadd_rn(ay, __fmul_rn(v, aby)), __fmul_rn(w, acy));
    float clz = __fadd_rn(__fadd_rn(az, __fmul_rn(v, abz)), __fmul_rn(w, acz));
    float dx = __fsub_rn(px, clx);
    float dy = __fsub_rn(py, cly);
    float dz = __fsub_rn(pz, clz);
    float dist2 = dot3(dx, dy, dz, dx, dy, dz);
    if (dist2 < best) {
        best = dist2;
        sd = dot3(dx, dy, dz, nx, ny, nz);
    }
}

__global__ void __launch_bounds__(TPB) sdf_partial(const float* __restrict__ points) {
    int p0 = blockIdx.x * (TPB * PPT) + threadIdx.x;
    int p1 = p0 + TPB;
    float px0 = points[p0 * 3 + 0], py0 = points[p0 * 3 + 1], pz0 = points[p0 * 3 + 2];
    float px1 = points[p1 * 3 + 0], py1 = points[p1 * 3 + 1], pz1 = points[p1 * 3 + 2];

    __shared__ float4 smem[TILE * 3];

    int fbase = blockIdx.y * FPS;
    float best0 = CUDART_INF_F, sd0 = 0.0f;
    float best1 = CUDART_INF_F, sd1 = 0.0f;

    for (int t0 = 0; t0 < FPS; t0 += TILE) {
        const float4* gsrc = reinterpret_cast<const float4*>(&g_tri[(fbase + t0) * 12]);
        #pragma unroll
        for (int k = 0; k < 3; k++) {
            smem[threadIdx.x + k * TPB] = gsrc[threadIdx.x + k * TPB];
        }
        __syncthreads();

        for (int j = 0; j < TILE; j++) {
            float4 q0 = smem[j * 3 + 0];
            float4 q1 = smem[j * 3 + 1];
            float4 q2 = smem[j * 3 + 2];
            float ax = q0.x, ay = q0.y, az = q0.z;
            float bx = q0.w, by = q1.x, bz = q1.y;
            float cx = q1.z, cy = q1.w, cz = q2.x;
            float nx = q2.y, ny = q2.z, nz = q2.w;

            // Triangle-local edges: shared across both points
            float abx = __fsub_rn(bx, ax), aby = __fsub_rn(by, ay), abz = __fsub_rn(bz, az);
            float acx = __fsub_rn(cx, ax), acy = __fsub_rn(cy, ay), acz = __fsub_rn(cz, az);

            eval_point(px0, py0, pz0, ax, ay, az, bx, by, bz, cx, cy, cz,
                       nx, ny, nz, abx, aby, abz, acx, acy, acz, best0, sd0);
            eval_point(px1, py1, pz1, ax, ay, az, bx, by, bz, cx, cy, cz,
                       nx, ny, nz, abx, aby, abz, acx, acy, acz, best1, sd1);
        }
        __syncthreads();
    }

    g_partial[blockIdx.y * NP + p0] = make_float2(best0, sd0);
    g_partial[blockIdx.y * NP + p1] = make_float2(best1, sd1);
}

__global__ void sdf_reduce(float* __restrict__ out) {
    int i = blockIdx.x * blockDim.x + threadIdx.x;
    if (i >= NP) return;
    float best = CUDART_INF_F;
    float sd = 0.0f;
    #pragma unroll
    for (int s = 0; s < NSPLIT; s++) {
        float2 v = g_partial[s * NP + i];
        if (v.x < best) { best = v.x; sd = v.y; }
    }
    float dist = sqrtf(fmaxf(best, 1e-12f));
    out[i] = (sd > 0.0f) ? -dist : dist;
}

extern "C" void kernel_launch(void* const* d_in, const int* in_sizes, int n_in,
                              void* d_out, int out_size) {
    const float* points   = (const float*)d_in[0];
    const float* vertices = (const float*)d_in[1];
    const int*   faces    = (const int*)d_in[2];
    float* out = (float*)d_out;

    precompute_tris<<<(NF + 255) / 256, 256>>>(vertices, faces);
    sdf_partial<<<dim3(NP / (TPB * PPT), NSPLIT), TPB>>>(points);
    sdf_reduce<<<(NP + 255) / 256, 256>>>(out);
}

// round 4
// speedup vs baseline: 1.3071x; 1.3071x over previous
#include <cuda_runtime.h>
#include <cuda_bf16.h>
#include <math_constants.h>

#define NV 8192
#define NF 16384
#define NP 16384
#define NSPLIT 8
#define SEEDSPLIT 8
#define TILE 256
#define TPB 256
#define FPS (NF / NSPLIT)       // 2048 triangles per split
#define SFPS (NF / SEEDSPLIT)   // 2048 faces per seed split
#define NBINS 32768             // 5 bits per axis Morton

// Packed per-triangle data: ax,ay,az, bx,by,bz, cx,cy,cz, nx,ny,nz
__device__ __align__(16) float g_tri[NF * 12];
__device__ float4 g_va[NF];    // vertex a (for seed pass)
__device__ float4 g_cull[NF];  // centroid xyz + inflated radius
__device__ unsigned int g_seed[NP];    // float bits of seed ub^2 (atomicMin)
__device__ unsigned int g_bins[NBINS];
__device__ unsigned int g_binoff[NBINS];
__device__ int g_pbin[NP];
__device__ int g_perm[NP];
__device__ float2 g_partial[NSPLIT * NP];  // indexed by sorted position

// ---------- strict IEEE helpers (bit-stable vs reference) ----------
__device__ __forceinline__ float dot3(float x0, float x1, float x2,
                                      float y0, float y1, float y2) {
    return __fadd_rn(__fadd_rn(__fmul_rn(x0, y0), __fmul_rn(x1, y1)),
                     __fmul_rn(x2, y2));
}
__device__ __forceinline__ float sdiv(float x, float y) {
    return __fdiv_rn(x, (y == 0.0f) ? 1.0f : y);
}

// ---------- kernel 1: triangle precompute ----------
__global__ void precompute_tris(const float* __restrict__ vertices,
                                const int* __restrict__ faces) {
    int f = blockIdx.x * blockDim.x + threadIdx.x;
    if (f >= NF) return;
    int i0 = faces[f * 3 + 0];
    int i1 = faces[f * 3 + 1];
    int i2 = faces[f * 3 + 2];
    float ax = vertices[i0 * 3 + 0], ay = vertices[i0 * 3 + 1], az = vertices[i0 * 3 + 2];
    float bx = vertices[i1 * 3 + 0], by = vertices[i1 * 3 + 1], bz = vertices[i1 * 3 + 2];
    float cx = vertices[i2 * 3 + 0], cy = vertices[i2 * 3 + 1], cz = vertices[i2 * 3 + 2];
    float abx = __fsub_rn(bx, ax), aby = __fsub_rn(by, ay), abz = __fsub_rn(bz, az);
    float acx = __fsub_rn(cx, ax), acy = __fsub_rn(cy, ay), acz = __fsub_rn(cz, az);
    float nx = __fsub_rn(__fmul_rn(aby, acz), __fmul_rn(abz, acy));
    float ny = __fsub_rn(__fmul_rn(abz, acx), __fmul_rn(abx, acz));
    float nz = __fsub_rn(__fmul_rn(abx, acy), __fmul_rn(aby, acx));
    float* t = &g_tri[f * 12];
    t[0] = ax; t[1] = ay; t[2] = az;
    t[3] = bx; t[4] = by; t[5] = bz;
    t[6] = cx; t[7] = cy; t[8] = cz;
    t[9] = nx; t[10] = ny; t[11] = nz;

    g_va[f] = make_float4(ax, ay, az, 0.0f);

    // bounding sphere: centroid + max vertex distance, inflated
    float ccx = (ax + bx + cx) * (1.0f / 3.0f);
    float ccy = (ay + by + cy) * (1.0f / 3.0f);
    float ccz = (az + bz + cz) * (1.0f / 3.0f);
    float da = sqrtf((ax-ccx)*(ax-ccx) + (ay-ccy)*(ay-ccy) + (az-ccz)*(az-ccz));
    float db = sqrtf((bx-ccx)*(bx-ccx) + (by-ccy)*(by-ccy) + (bz-ccz)*(bz-ccz));
    float dc = sqrtf((cx-ccx)*(cx-ccx) + (cy-ccy)*(cy-ccy) + (cz-ccz)*(cz-ccz));
    float r = fmaxf(da, fmaxf(db, dc));
    g_cull[f] = make_float4(ccx, ccy, ccz, r * 1.001f + 1e-5f);
}

// ---------- kernel 2: init bins + seeds ----------
__global__ void init_arrays() {
    int i = blockIdx.x * blockDim.x + threadIdx.x;
    if (i < NBINS) g_bins[i] = 0;
    if (i < NP) g_seed[i] = 0x7F800000u;  // +inf
}

// ---------- kernel 3: Morton histogram ----------
__device__ __forceinline__ int quant5(float x) {
    int v = (int)((x + 6.0f) * (32.0f / 12.0f));
    return min(31, max(0, v));
}
__global__ void morton_hist(const float* __restrict__ points) {
    int i = blockIdx.x * blockDim.x + threadIdx.x;
    if (i >= NP) return;
    int qx = quant5(points[i * 3 + 0]);
    int qy = quant5(points[i * 3 + 1]);
    int qz = quant5(points[i * 3 + 2]);
    int m = 0;
    #pragma unroll
    for (int b = 0; b < 5; b++) {
        m |= ((qx >> b) & 1) << (3 * b);
        m |= ((qy >> b) & 1) << (3 * b + 1);
        m |= ((qz >> b) & 1) << (3 * b + 2);
    }
    g_pbin[i] = m;
    atomicAdd(&g_bins[m], 1u);
}

// ---------- kernel 4: exclusive scan of bins (single block) ----------
__global__ void __launch_bounds__(1024) scan_bins() {
    __shared__ unsigned int s[1024];
    int t = threadIdx.x;
    unsigned int loc[NBINS / 1024];
    unsigned int sum = 0;
    #pragma unroll
    for (int k = 0; k < NBINS / 1024; k++) {
        loc[k] = g_bins[t * (NBINS / 1024) + k];
        sum += loc[k];
    }
    s[t] = sum;
    __syncthreads();
    for (int off = 1; off < 1024; off <<= 1) {
        unsigned int v = (t >= off) ? s[t - off] : 0u;
        __syncthreads();
        s[t] += v;
        __syncthreads();
    }
    unsigned int run = s[t] - sum;  // exclusive
    #pragma unroll
    for (int k = 0; k < NBINS / 1024; k++) {
        g_binoff[t * (NBINS / 1024) + k] = run;
        run += loc[k];
    }
}

// ---------- kernel 5: scatter permutation ----------
__global__ void scatter_perm() {
    int i = blockIdx.x * blockDim.x + threadIdx.x;
    if (i >= NP) return;
    unsigned int pos = atomicAdd(&g_binoff[g_pbin[i]], 1u);
    g_perm[pos] = i;
}

// ---------- kernel 6: seed pass (upper bound via vertex a) ----------
__global__ void __launch_bounds__(TPB) seed_pass(const float* __restrict__ points) {
    int i = blockIdx.x * TPB + threadIdx.x;
    float px = points[i * 3 + 0];
    float py = points[i * 3 + 1];
    float pz = points[i * 3 + 2];
    __shared__ float4 sva[TILE];
    int fbase = blockIdx.y * SFPS;
    float m = CUDART_INF_F;
    for (int t0 = 0; t0 < SFPS; t0 += TILE) {
        sva[threadIdx.x] = g_va[fbase + t0 + threadIdx.x];
        __syncthreads();
        #pragma unroll 8
        for (int j = 0; j < TILE; j++) {
            float4 a = sva[j];
            float dx = px - a.x, dy = py - a.y, dz = pz - a.z;
            float d2 = fmaf(dx, dx, fmaf(dy, dy, dz * dz));
            m = fminf(m, d2);
        }
        __syncthreads();
    }
    atomicMin(&g_seed[i], __float_as_uint(m));  // positive floats: uint order == float order
}

// ---------- kernel 7: main pass (R2 eval body, verbatim, under cull) ----------
__global__ void __launch_bounds__(TPB) sdf_partial(const float* __restrict__ points) {
    int pos = blockIdx.x * TPB + threadIdx.x;
    int pid = g_perm[pos];
    float px = points[pid * 3 + 0];
    float py = points[pid * 3 + 1];
    float pz = points[pid * 3 + 2];

    __shared__ float4 smem[TILE * 3];
    __shared__ float4 scull[TILE];

    int fbase = blockIdx.y * FPS;
    float best = CUDART_INF_F;
    float sd = 0.0f;
    // inflated upper bound on winning distance (from seed)
    float sq = fmaf(sqrtf(__uint_as_float(g_seed[pid])), 1.001f, 1e-6f);

    for (int t0 = 0; t0 < FPS; t0 += TILE) {
        const float4* gsrc = reinterpret_cast<const float4*>(&g_tri[(fbase + t0) * 12]);
        #pragma unroll
        for (int k = 0; k < 3; k++) {
            smem[threadIdx.x + k * TPB] = gsrc[threadIdx.x + k * TPB];
        }
        scull[threadIdx.x] = g_cull[fbase + t0 + threadIdx.x];
        __syncthreads();

        for (int j = 0; j < TILE; j++) {
            // conservative bounding-sphere cull (margins >> fp noise)
            float4 cc = scull[j];
            float ex = px - cc.x, ey = py - cc.y, ez = pz - cc.z;
            float d2c = fmaf(ex, ex, fmaf(ey, ey, ez * ez));
            float rhs = sq + cc.w;
            if (d2c > rhs * rhs) continue;

            float4 q0 = smem[j * 3 + 0];
            float4 q1 = smem[j * 3 + 1];
            float4 q2 = smem[j * 3 + 2];
            float ax = q0.x, ay = q0.y, az = q0.z;
            float bx = q0.w, by = q1.x, bz = q1.y;
            float cx = q1.z, cy = q1.w, cz = q2.x;
            float nx = q2.y, ny = q2.z, nz = q2.w;

            float abx = __fsub_rn(bx, ax), aby = __fsub_rn(by, ay), abz = __fsub_rn(bz, az);
            float acx = __fsub_rn(cx, ax), acy = __fsub_rn(cy, ay), acz = __fsub_rn(cz, az);
            float apx = __fsub_rn(px, ax), apy = __fsub_rn(py, ay), apz = __fsub_rn(pz, az);
            float bpx = __fsub_rn(px, bx), bpy = __fsub_rn(py, by), bpz = __fsub_rn(pz, bz);
            float cpx = __fsub_rn(px, cx), cpy = __fsub_rn(py, cy), cpz = __fsub_rn(pz, cz);

            float d1 = dot3(abx, aby, abz, apx, apy, apz);
            float d2 = dot3(acx, acy, acz, apx, apy, apz);
            float d3 = dot3(abx, aby, abz, bpx, bpy, bpz);
            float d4 = dot3(acx, acy, acz, bpx, bpy, bpz);
            float d5 = dot3(abx, aby, abz, cpx, cpy, cpz);
            float d6 = dot3(acx, acy, acz, cpx, cpy, cpz);

            float va = __fsub_rn(__fmul_rn(d3, d6), __fmul_rn(d5, d4));
            float vb = __fsub_rn(__fmul_rn(d5, d2), __fmul_rn(d1, d6));
            float vc = __fsub_rn(__fmul_rn(d1, d4), __fmul_rn(d3, d2));
            float denom = __fadd_rn(__fadd_rn(va, vb), vc);
            float v = sdiv(vb, denom);
            float w = sdiv(vc, denom);

            float e43 = __fsub_rn(d4, d3);
            float e56 = __fsub_rn(d5, d6);
            float t_bc = sdiv(e43, __fadd_rn(e43, e56));
            if (va <= 0.0f && e43 >= 0.0f && e56 >= 0.0f) {
                v = __fsub_rn(1.0f, t_bc); w = t_bc;
            }
            float t_ac = sdiv(d2, __fsub_rn(d2, d6));
            if (vb <= 0.0f && d2 >= 0.0f && d6 <= 0.0f) { v = 0.0f; w = t_ac; }
            float t_ab = sdiv(d1, __fsub_rn(d1, d3));
            if (vc <= 0.0f && d1 >= 0.0f && d3 <= 0.0f) { v = t_ab; w = 0.0f; }
            if (d6 >= 0.0f && d5 <= d6) { v = 0.0f; w = 1.0f; }
            if (d3 >= 0.0f && d4 <= d3) { v = 1.0f; w = 0.0f; }
            if (d1 <= 0.0f && d2 <= 0.0f) { v = 0.0f; w = 0.0f; }

            float clx = __fadd_rn(__fadd_rn(ax, __fmul_rn(v, abx)), __fmul_rn(w, acx));
            float cly = __fadd_rn(__fadd_rn(ay, __fmul_rn(v, aby)), __fmul_rn(w, acy));
            float clz = __fadd_rn(__fadd_rn(az, __fmul_rn(v, abz)), __fmul_rn(w, acz));
            float dx = __fsub_rn(px, clx);
            float dy = __fsub_rn(py, cly);
            float dz = __fsub_rn(pz, clz);
            float dist2 = dot3(dx, dy, dz, dx, dy, dz);
            if (dist2 < best) {
                best = dist2;
                sd = dot3(dx, dy, dz, nx, ny, nz);
                sq = fminf(sq, fmaf(sqrtf(dist2), 1.001f, 1e-6f));
            }
        }
        __syncthreads();
    }

    g_partial[blockIdx.y * NP + pos] = make_float2(best, sd);
}

// ---------- kernel 8: reduce over splits ----------
__global__ void sdf_reduce(float* __restrict__ out) {
    int pos = blockIdx.x * blockDim.x + threadIdx.x;
    if (pos >= NP) return;
    float best = CUDART_INF_F;
    float sd = 0.0f;
    #pragma unroll
    for (int s = 0; s < NSPLIT; s++) {
        float2 v = g_partial[s * NP + pos];
        if (v.x < best) { best = v.x; sd = v.y; }
    }
    float dist = sqrtf(fmaxf(best, 1e-12f));
    out[g_perm[pos]] = (sd > 0.0f) ? -dist : dist;
}

extern "C" void kernel_launch(void* const* d_in, const int* in_sizes, int n_in,
                              void* d_out, int out_size) {
    const float* points   = (const float*)d_in[0];
    const float* vertices = (const float*)d_in[1];
    const int*   faces    = (const int*)d_in[2];
    float* out = (float*)d_out;

    precompute_tris<<<(NF + 255) / 256, 256>>>(vertices, faces);
    init_arrays<<<(NBINS + 255) / 256, 256>>>();
    morton_hist<<<(NP + 255) / 256, 256>>>(points);
    scan_bins<<<1, 1024>>>();
    scatter_perm<<<(NP + 255) / 256, 256>>>();
    seed_pass<<<dim3(NP / TPB, SEEDSPLIT), TPB>>>(points);
    sdf_partial<<<dim3(NP / TPB, NSPLIT), TPB>>>(points);
    sdf_reduce<<<(NP + 255) / 256, 256>>>(out);
}

// round 5
// speedup vs baseline: 4.8301x; 3.6953x over previous
#include <cuda_runtime.h>
#include <cuda_bf16.h>
#include <math_constants.h>

#define NV 8192
#define NF 16384
#define NP 16384
#define TPB 256
#define WPB (TPB / 32)

// Packed per-triangle data: ax,ay,az, bx,by,bz, cx,cy,cz, nx,ny,nz
__device__ __align__(16) float g_tri[NF * 12];
// Plane cull data: unit normal xyz, d = dot(a, n_hat). Zero if degenerate.
__device__ float4 g_plane[NF];

// ---------- strict IEEE helpers (bit-stable vs reference) ----------
__device__ __forceinline__ float dot3(float x0, float x1, float x2,
                                      float y0, float y1, float y2) {
    return __fadd_rn(__fadd_rn(__fmul_rn(x0, y0), __fmul_rn(x1, y1)),
                     __fmul_rn(x2, y2));
}
__device__ __forceinline__ float sdiv(float x, float y) {
    return __fdiv_rn(x, (y == 0.0f) ? 1.0f : y);
}

// ---------- kernel 1: triangle precompute ----------
__global__ void precompute_tris(const float* __restrict__ vertices,
                                const int* __restrict__ faces) {
    int f = blockIdx.x * blockDim.x + threadIdx.x;
    if (f >= NF) return;
    int i0 = faces[f * 3 + 0];
    int i1 = faces[f * 3 + 1];
    int i2 = faces[f * 3 + 2];
    float ax = vertices[i0 * 3 + 0], ay = vertices[i0 * 3 + 1], az = vertices[i0 * 3 + 2];
    float bx = vertices[i1 * 3 + 0], by = vertices[i1 * 3 + 1], bz = vertices[i1 * 3 + 2];
    float cx = vertices[i2 * 3 + 0], cy = vertices[i2 * 3 + 1], cz = vertices[i2 * 3 + 2];
    float abx = __fsub_rn(bx, ax), aby = __fsub_rn(by, ay), abz = __fsub_rn(bz, az);
    float acx = __fsub_rn(cx, ax), acy = __fsub_rn(cy, ay), acz = __fsub_rn(cz, az);
    float nx = __fsub_rn(__fmul_rn(aby, acz), __fmul_rn(abz, acy));
    float ny = __fsub_rn(__fmul_rn(abz, acx), __fmul_rn(abx, acz));
    float nz = __fsub_rn(__fmul_rn(abx, acy), __fmul_rn(aby, acx));
    float* t = &g_tri[f * 12];
    t[0] = ax; t[1] = ay; t[2] = az;
    t[3] = bx; t[4] = by; t[5] = bz;
    t[6] = cx; t[7] = cy; t[8] = cz;
    t[9] = nx; t[10] = ny; t[11] = nz;

    // Plane for culling (approx math fine: used only behind safety margins)
    float len2 = nx * nx + ny * ny + nz * nz;
    if (len2 > 0.0f) {
        float inv = rsqrtf(len2);
        float ux = nx * inv, uy = ny * inv, uz = nz * inv;
        float d = ax * ux + ay * uy + az * uz;
        g_plane[f] = make_float4(ux, uy, uz, d);
    } else {
        g_plane[f] = make_float4(0.0f, 0.0f, 0.0f, 0.0f);  // never culled
    }
}

// Evaluate one triangle exactly (bit-identical to reference); update lane best.
__device__ __forceinline__ void eval_tri(
    int fe, float px, float py, float pz,
    unsigned long long& best_key, float& best_sd)
{
    const float4* tq = reinterpret_cast<const float4*>(&g_tri[fe * 12]);
    float4 q0 = __ldg(&tq[0]);
    float4 q1 = __ldg(&tq[1]);
    float4 q2 = __ldg(&tq[2]);
    float ax = q0.x, ay = q0.y, az = q0.z;
    float bx = q0.w, by = q1.x, bz = q1.y;
    float cx = q1.z, cy = q1.w, cz = q2.x;
    float nx = q2.y, ny = q2.z, nz = q2.w;

    float abx = __fsub_rn(bx, ax), aby = __fsub_rn(by, ay), abz = __fsub_rn(bz, az);
    float acx = __fsub_rn(cx, ax), acy = __fsub_rn(cy, ay), acz = __fsub_rn(cz, az);
    float apx = __fsub_rn(px, ax), apy = __fsub_rn(py, ay), apz = __fsub_rn(pz, az);
    float bpx = __fsub_rn(px, bx), bpy = __fsub_rn(py, by), bpz = __fsub_rn(pz, bz);
    float cpx = __fsub_rn(px, cx), cpy = __fsub_rn(py, cy), cpz = __fsub_rn(pz, cz);

    float d1 = dot3(abx, aby, abz, apx, apy, apz);
    float d2 = dot3(acx, acy, acz, apx, apy, apz);
    float d3 = dot3(abx, aby, abz, bpx, bpy, bpz);
    float d4 = dot3(acx, acy, acz, bpx, bpy, bpz);
    float d5 = dot3(abx, aby, abz, cpx, cpy, cpz);
    float d6 = dot3(acx, acy, acz, cpx, cpy, cpz);

    float va = __fsub_rn(__fmul_rn(d3, d6), __fmul_rn(d5, d4));
    float vb = __fsub_rn(__fmul_rn(d5, d2), __fmul_rn(d1, d6));
    float vc = __fsub_rn(__fmul_rn(d1, d4), __fmul_rn(d3, d2));
    float denom = __fadd_rn(__fadd_rn(va, vb), vc);
    float v = sdiv(vb, denom);
    float w = sdiv(vc, denom);

    float e43 = __fsub_rn(d4, d3);
    float e56 = __fsub_rn(d5, d6);
    float t_bc = sdiv(e43, __fadd_rn(e43, e56));
    if (va <= 0.0f && e43 >= 0.0f && e56 >= 0.0f) {
        v = __fsub_rn(1.0f, t_bc); w = t_bc;
    }
    float t_ac = sdiv(d2, __fsub_rn(d2, d6));
    if (vb <= 0.0f && d2 >= 0.0f && d6 <= 0.0f) { v = 0.0f; w = t_ac; }
    float t_ab = sdiv(d1, __fsub_rn(d1, d3));
    if (vc <= 0.0f && d1 >= 0.0f && d3 <= 0.0f) { v = t_ab; w = 0.0f; }
    if (d6 >= 0.0f && d5 <= d6) { v = 0.0f; w = 1.0f; }
    if (d3 >= 0.0f && d4 <= d3) { v = 1.0f; w = 0.0f; }
    if (d1 <= 0.0f && d2 <= 0.0f) { v = 0.0f; w = 0.0f; }

    float clx = __fadd_rn(__fadd_rn(ax, __fmul_rn(v, abx)), __fmul_rn(w, acx));
    float cly = __fadd_rn(__fadd_rn(ay, __fmul_rn(v, aby)), __fmul_rn(w, acy));
    float clz = __fadd_rn(__fadd_rn(az, __fmul_rn(v, abz)), __fmul_rn(w, acz));
    float dx = __fsub_rn(px, clx);
    float dy = __fsub_rn(py, cly);
    float dz = __fsub_rn(pz, clz);
    float dist2 = dot3(dx, dy, dz, dx, dy, dz);

    unsigned long long key =
        ((unsigned long long)__float_as_uint(dist2) << 32) | (unsigned)fe;
    if (key < best_key) {
        best_key = key;
        best_sd = dot3(dx, dy, dz, nx, ny, nz);
    }
}

// ---------- kernel 2: warp-per-point with plane cull + survivor compaction ----
__global__ void __launch_bounds__(TPB) sdf_main(const float* __restrict__ points,
                                                float* __restrict__ out) {
    __shared__ int queue[WPB][64];

    int warp_in_blk = threadIdx.x / 32;
    int lane = threadIdx.x % 32;
    int pid = blockIdx.x * WPB + warp_in_blk;

    float px = points[pid * 3 + 0];
    float py = points[pid * 3 + 1];
    float pz = points[pid * 3 + 2];

    // Seed upper bound from 1024 vertex-a distances (any vertex dist >= true min)
    float ub2 = CUDART_INF_F;
    #pragma unroll 4
    for (int i = 0; i < 32; i++) {
        int f = i * 32 + lane;
        const float4* tq = reinterpret_cast<const float4*>(&g_tri[f * 12]);
        float4 q0 = __ldg(&tq[0]);
        float dx = px - q0.x, dy = py - q0.y, dz = pz - q0.z;
        ub2 = fminf(ub2, fmaf(dx, dx, fmaf(dy, dy, dz * dz)));
    }
    #pragma unroll
    for (int o = 16; o > 0; o >>= 1)
        ub2 = fminf(ub2, __shfl_xor_sync(0xFFFFFFFFu, ub2, o));
    float sq = fmaf(sqrtf(ub2), 1.001f, 1e-6f);  // inflated upper bound on min dist

    unsigned long long best_key = 0xFFFFFFFFFFFFFFFFull;
    float best_sd = 0.0f;

    int qn = 0, qhead = 0;

    for (int chunk = 0; chunk < NF; chunk += 32) {
        int f = chunk + lane;
        float4 pl = __ldg(&g_plane[f]);
        float pd = fabsf(fmaf(px, pl.x, fmaf(py, pl.y, fmaf(pz, pl.z, -pl.w))));
        bool keep = (pd <= sq);
        unsigned mask = __ballot_sync(0xFFFFFFFFu, keep);
        if (keep) {
            int pos = (qhead + qn + __popc(mask & ((1u << lane) - 1u))) & 63;
            queue[warp_in_blk][pos] = f;
        }
        qn += __popc(mask);
        __syncwarp();

        if (qn >= 32) {
            int fe = queue[warp_in_blk][(qhead + lane) & 63];
            __syncwarp();
            qhead = (qhead + 32) & 63;
            qn -= 32;
            eval_tri(fe, px, py, pz, best_key, best_sd);
            // tighten sq from warp-wide best
            float bd2 = __uint_as_float((unsigned)(best_key >> 32));
            #pragma unroll
            for (int o = 16; o > 0; o >>= 1)
                bd2 = fminf(bd2, __shfl_xor_sync(0xFFFFFFFFu, bd2, o));
            sq = fminf(sq, fmaf(sqrtf(bd2), 1.001f, 1e-6f));
        }
    }

    // Drain remaining queued survivors
    if (lane < qn) {
        int fe = queue[warp_in_blk][(qhead + lane) & 63];
        eval_tri(fe, px, py, pz, best_key, best_sd);
    }
    __syncwarp();

    // Warp-reduce (key, sd) lexicographic min — matches argmin first-index tie-break
    #pragma unroll
    for (int o = 16; o > 0; o >>= 1) {
        unsigned long long ok = __shfl_xor_sync(0xFFFFFFFFu, best_key, o);
        float osd = __shfl_xor_sync(0xFFFFFFFFu, best_sd, o);
        if (ok < best_key) { best_key = ok; best_sd = osd; }
    }

    if (lane == 0) {
        float dist2 = __uint_as_float((unsigned)(best_key >> 32));
        float dist = sqrtf(fmaxf(dist2, 1e-12f));
        out[pid] = (best_sd > 0.0f) ? -dist : dist;
    }
}

extern "C" void kernel_launch(void* const* d_in, const int* in_sizes, int n_in,
                              void* d_out, int out_size) {
    const float* points   = (const float*)d_in[0];
    const float* vertices = (const float*)d_in[1];
    const int*   faces    = (const int*)d_in[2];
    float* out = (float*)d_out;

    precompute_tris<<<(NF + 255) / 256, 256>>>(vertices, faces);
    sdf_main<<<NP / WPB, TPB>>>(points, out);
}

// round 6
// speedup vs baseline: 6.2252x; 1.2888x over previous
#include <cuda_runtime.h>
#include <cuda_bf16.h>
#include <math_constants.h>

#define NV 8192
#define NF 16384
#define NP 16384
#define TPB 128
#define WPB (TPB / 32)
#define QCAP 128

// Packed per-triangle data: ax,ay,az, bx,by,bz, cx,cy,cz, nx,ny,nz
__device__ __align__(16) float g_tri[NF * 12];
// Plane cull data: unit normal xyz, d = dot(a, n_hat). Zero if degenerate.
__device__ float4 g_plane[NF];

// ---------- strict IEEE helpers (bit-stable vs reference) ----------
__device__ __forceinline__ float dot3(float x0, float x1, float x2,
                                      float y0, float y1, float y2) {
    return __fadd_rn(__fadd_rn(__fmul_rn(x0, y0), __fmul_rn(x1, y1)),
                     __fmul_rn(x2, y2));
}
__device__ __forceinline__ float sdiv(float x, float y) {
    return __fdiv_rn(x, (y == 0.0f) ? 1.0f : y);
}

// ---------- kernel 1: triangle precompute ----------
__global__ void precompute_tris(const float* __restrict__ vertices,
                                const int* __restrict__ faces) {
    int f = blockIdx.x * blockDim.x + threadIdx.x;
    if (f >= NF) return;
    int i0 = faces[f * 3 + 0];
    int i1 = faces[f * 3 + 1];
    int i2 = faces[f * 3 + 2];
    float ax = vertices[i0 * 3 + 0], ay = vertices[i0 * 3 + 1], az = vertices[i0 * 3 + 2];
    float bx = vertices[i1 * 3 + 0], by = vertices[i1 * 3 + 1], bz = vertices[i1 * 3 + 2];
    float cx = vertices[i2 * 3 + 0], cy = vertices[i2 * 3 + 1], cz = vertices[i2 * 3 + 2];
    float abx = __fsub_rn(bx, ax), aby = __fsub_rn(by, ay), abz = __fsub_rn(bz, az);
    float acx = __fsub_rn(cx, ax), acy = __fsub_rn(cy, ay), acz = __fsub_rn(cz, az);
    float nx = __fsub_rn(__fmul_rn(aby, acz), __fmul_rn(abz, acy));
    float ny = __fsub_rn(__fmul_rn(abz, acx), __fmul_rn(abx, acz));
    float nz = __fsub_rn(__fmul_rn(abx, acy), __fmul_rn(aby, acx));
    float* t = &g_tri[f * 12];
    t[0] = ax; t[1] = ay; t[2] = az;
    t[3] = bx; t[4] = by; t[5] = bz;
    t[6] = cx; t[7] = cy; t[8] = cz;
    t[9] = nx; t[10] = ny; t[11] = nz;

    // Plane for culling (approx math fine: used only behind safety margins)
    float len2 = nx * nx + ny * ny + nz * nz;
    if (len2 > 0.0f) {
        float inv = rsqrtf(len2);
        float ux = nx * inv, uy = ny * inv, uz = nz * inv;
        float d = ax * ux + ay * uy + az * uz;
        g_plane[f] = make_float4(ux, uy, uz, -d);
    } else {
        g_plane[f] = make_float4(0.0f, 0.0f, 0.0f, 0.0f);  // never culled
    }
}

// Evaluate one triangle exactly (bit-identical to reference); update lane best.
// Returns true if this lane's best improved.
__device__ __forceinline__ bool eval_tri(
    int fe, float px, float py, float pz,
    unsigned long long& best_key, float& best_sd)
{
    const float4* tq = reinterpret_cast<const float4*>(&g_tri[fe * 12]);
    float4 q0 = __ldg(&tq[0]);
    float4 q1 = __ldg(&tq[1]);
    float4 q2 = __ldg(&tq[2]);
    float ax = q0.x, ay = q0.y, az = q0.z;
    float bx = q0.w, by = q1.x, bz = q1.y;
    float cx = q1.z, cy = q1.w, cz = q2.x;
    float nx = q2.y, ny = q2.z, nz = q2.w;

    float abx = __fsub_rn(bx, ax), aby = __fsub_rn(by, ay), abz = __fsub_rn(bz, az);
    float acx = __fsub_rn(cx, ax), acy = __fsub_rn(cy, ay), acz = __fsub_rn(cz, az);
    float apx = __fsub_rn(px, ax), apy = __fsub_rn(py, ay), apz = __fsub_rn(pz, az);
    float bpx = __fsub_rn(px, bx), bpy = __fsub_rn(py, by), bpz = __fsub_rn(pz, bz);
    float cpx = __fsub_rn(px, cx), cpy = __fsub_rn(py, cy), cpz = __fsub_rn(pz, cz);

    float d1 = dot3(abx, aby, abz, apx, apy, apz);
    float d2 = dot3(acx, acy, acz, apx, apy, apz);
    float d3 = dot3(abx, aby, abz, bpx, bpy, bpz);
    float d4 = dot3(acx, acy, acz, bpx, bpy, bpz);
    float d5 = dot3(abx, aby, abz, cpx, cpy, cpz);
    float d6 = dot3(acx, acy, acz, cpx, cpy, cpz);

    float va = __fsub_rn(__fmul_rn(d3, d6), __fmul_rn(d5, d4));
    float vb = __fsub_rn(__fmul_rn(d5, d2), __fmul_rn(d1, d6));
    float vc = __fsub_rn(__fmul_rn(d1, d4), __fmul_rn(d3, d2));
    float denom = __fadd_rn(__fadd_rn(va, vb), vc);
    float v = sdiv(vb, denom);
    float w = sdiv(vc, denom);

    float e43 = __fsub_rn(d4, d3);
    float e56 = __fsub_rn(d5, d6);
    float t_bc = sdiv(e43, __fadd_rn(e43, e56));
    if (va <= 0.0f && e43 >= 0.0f && e56 >= 0.0f) {
        v = __fsub_rn(1.0f, t_bc); w = t_bc;
    }
    float t_ac = sdiv(d2, __fsub_rn(d2, d6));
    if (vb <= 0.0f && d2 >= 0.0f && d6 <= 0.0f) { v = 0.0f; w = t_ac; }
    float t_ab = sdiv(d1, __fsub_rn(d1, d3));
    if (vc <= 0.0f && d1 >= 0.0f && d3 <= 0.0f) { v = t_ab; w = 0.0f; }
    if (d6 >= 0.0f && d5 <= d6) { v = 0.0f; w = 1.0f; }
    if (d3 >= 0.0f && d4 <= d3) { v = 1.0f; w = 0.0f; }
    if (d1 <= 0.0f && d2 <= 0.0f) { v = 0.0f; w = 0.0f; }

    float clx = __fadd_rn(__fadd_rn(ax, __fmul_rn(v, abx)), __fmul_rn(w, acx));
    float cly = __fadd_rn(__fadd_rn(ay, __fmul_rn(v, aby)), __fmul_rn(w, acy));
    float clz = __fadd_rn(__fadd_rn(az, __fmul_rn(v, abz)), __fmul_rn(w, acz));
    float dx = __fsub_rn(px, clx);
    float dy = __fsub_rn(py, cly);
    float dz = __fsub_rn(pz, clz);
    float dist2 = dot3(dx, dy, dz, dx, dy, dz);

    unsigned long long key =
        ((unsigned long long)__float_as_uint(dist2) << 32) | (unsigned)fe;
    if (key < best_key) {
        best_key = key;
        best_sd = dot3(dx, dy, dz, nx, ny, nz);
        return true;
    }
    return false;
}

// ---------- kernel 2: warp-per-point, 2-wide plane cull + compaction ----------
__global__ void __launch_bounds__(TPB) sdf_main(const float* __restrict__ points,
                                                float* __restrict__ out) {
    __shared__ int queue[WPB][QCAP];

    int warp_in_blk = threadIdx.x / 32;
    int lane = threadIdx.x % 32;
    int pid = blockIdx.x * WPB + warp_in_blk;

    float px = points[pid * 3 + 0];
    float py = points[pid * 3 + 1];
    float pz = points[pid * 3 + 2];

    // Seed upper bound from 1024 vertex-a distances
    float ub2 = CUDART_INF_F;
    #pragma unroll 4
    for (int i = 0; i < 32; i++) {
        int f = i * 32 + lane;
        const float4* tq = reinterpret_cast<const float4*>(&g_tri[f * 12]);
        float4 q0 = __ldg(&tq[0]);
        float dx = px - q0.x, dy = py - q0.y, dz = pz - q0.z;
        ub2 = fminf(ub2, fmaf(dx, dx, fmaf(dy, dy, dz * dz)));
    }
    #pragma unroll
    for (int o = 16; o > 0; o >>= 1)
        ub2 = fminf(ub2, __shfl_xor_sync(0xFFFFFFFFu, ub2, o));
    float sq = fmaf(sqrtf(ub2), 1.001f, 1e-6f);  // inflated upper bound on min dist

    unsigned long long best_key = 0xFFFFFFFFFFFFFFFFull;
    float best_sd = 0.0f;

    int qn = 0, qhead = 0;
    unsigned lanemask = (1u << lane) - 1u;

    for (int chunk = 0; chunk < NF; chunk += 64) {
        int f0 = chunk + lane;
        int f1 = f0 + 32;
        float4 pl0 = __ldg(&g_plane[f0]);
        float4 pl1 = __ldg(&g_plane[f1]);
        float pd0 = fabsf(fmaf(px, pl0.x, fmaf(py, pl0.y, fmaf(pz, pl0.z, pl0.w))));
        float pd1 = fabsf(fmaf(px, pl1.x, fmaf(py, pl1.y, fmaf(pz, pl1.z, pl1.w))));
        bool k0 = (pd0 <= sq);
        bool k1 = (pd1 <= sq);
        unsigned m0 = __ballot_sync(0xFFFFFFFFu, k0);
        unsigned m1 = __ballot_sync(0xFFFFFFFFu, k1);
        int n0 = __popc(m0);
        if (k0) queue[warp_in_blk][(qhead + qn + __popc(m0 & lanemask)) & (QCAP - 1)] = f0;
        if (k1) queue[warp_in_blk][(qhead + qn + n0 + __popc(m1 & lanemask)) & (QCAP - 1)] = f1;
        qn += n0 + __popc(m1);
        __syncwarp();

        while (qn >= 32) {
            int fe = queue[warp_in_blk][(qhead + lane) & (QCAP - 1)];
            qhead += 32;
            qn -= 32;
            bool improved = eval_tri(fe, px, py, pz, best_key, best_sd);
            // tighten sq only if someone improved
            if (__ballot_sync(0xFFFFFFFFu, improved)) {
                float bd2 = __uint_as_float((unsigned)(best_key >> 32));
                #pragma unroll
                for (int o = 16; o > 0; o >>= 1)
                    bd2 = fminf(bd2, __shfl_xor_sync(0xFFFFFFFFu, bd2, o));
                sq = fminf(sq, fmaf(sqrtf(bd2), 1.001f, 1e-6f));
            }
        }
        __syncwarp();
    }

    // Drain remaining queued survivors
    if (lane < qn) {
        int fe = queue[warp_in_blk][(qhead + lane) & (QCAP - 1)];
        eval_tri(fe, px, py, pz, best_key, best_sd);
    }
    __syncwarp();

    // Warp-reduce (key, sd) lexicographic min — matches argmin first-index tie-break
    #pragma unroll
    for (int o = 16; o > 0; o >>= 1) {
        unsigned long long ok = __shfl_xor_sync(0xFFFFFFFFu, best_key, o);
        float osd = __shfl_xor_sync(0xFFFFFFFFu, best_sd, o);
        if (ok < best_key) { best_key = ok; best_sd = osd; }
    }

    if (lane == 0) {
        float dist2 = __uint_as_float((unsigned)(best_key >> 32));
        float dist = sqrtf(fmaxf(dist2, 1e-12f));
        out[pid] = (best_sd > 0.0f) ? -dist : dist;
    }
}

extern "C" void kernel_launch(void* const* d_in, const int* in_sizes, int n_in,
                              void* d_out, int out_size) {
    const float* points   = (const float*)d_in[0];
    const float* vertices = (const float*)d_in[1];
    const int*   faces    = (const int*)d_in[2];
    float* out = (float*)d_out;

    precompute_tris<<<(NF + 255) / 256, 256>>>(vertices, faces);
    sdf_main<<<NP / WPB, TPB>>>(points, out);
}

// round 7
// speedup vs baseline: 8.0676x; 1.2959x over previous
#include <cuda_runtime.h>
#include <cuda_bf16.h>
#include <math_constants.h>

#define NV 8192
#define NF 16384
#define NP 16384
#define TPB 128
#define WPB (TPB / 32)
#define QCAP 256

// Packed per-triangle data: ax,ay,az, bx,by,bz, cx,cy,cz, nx,ny,nz
__device__ __align__(16) float g_tri[NF * 12];
// Plane cull data: unit normal xyz, w = -dot(a, n_hat). Zero if degenerate.
__device__ float4 g_plane[NF];

// ---------- strict IEEE helpers (bit-stable vs reference) ----------
__device__ __forceinline__ float dot3(float x0, float x1, float x2,
                                      float y0, float y1, float y2) {
    return __fadd_rn(__fadd_rn(__fmul_rn(x0, y0), __fmul_rn(x1, y1)),
                     __fmul_rn(x2, y2));
}
__device__ __forceinline__ float sdiv(float x, float y) {
    return __fdiv_rn(x, (y == 0.0f) ? 1.0f : y);
}

// ---------- kernel 1: triangle precompute ----------
__global__ void precompute_tris(const float* __restrict__ vertices,
                                const int* __restrict__ faces) {
    int f = blockIdx.x * blockDim.x + threadIdx.x;
    if (f >= NF) return;
    int i0 = faces[f * 3 + 0];
    int i1 = faces[f * 3 + 1];
    int i2 = faces[f * 3 + 2];
    float ax = vertices[i0 * 3 + 0], ay = vertices[i0 * 3 + 1], az = vertices[i0 * 3 + 2];
    float bx = vertices[i1 * 3 + 0], by = vertices[i1 * 3 + 1], bz = vertices[i1 * 3 + 2];
    float cx = vertices[i2 * 3 + 0], cy = vertices[i2 * 3 + 1], cz = vertices[i2 * 3 + 2];
    float abx = __fsub_rn(bx, ax), aby = __fsub_rn(by, ay), abz = __fsub_rn(bz, az);
    float acx = __fsub_rn(cx, ax), acy = __fsub_rn(cy, ay), acz = __fsub_rn(cz, az);
    float nx = __fsub_rn(__fmul_rn(aby, acz), __fmul_rn(abz, acy));
    float ny = __fsub_rn(__fmul_rn(abz, acx), __fmul_rn(abx, acz));
    float nz = __fsub_rn(__fmul_rn(abx, acy), __fmul_rn(aby, acx));
    float* t = &g_tri[f * 12];
    t[0] = ax; t[1] = ay; t[2] = az;
    t[3] = bx; t[4] = by; t[5] = bz;
    t[6] = cx; t[7] = cy; t[8] = cz;
    t[9] = nx; t[10] = ny; t[11] = nz;

    // Plane for culling (approx math fine: used only behind safety margins)
    float len2 = nx * nx + ny * ny + nz * nz;
    if (len2 > 0.0f) {
        float inv = rsqrtf(len2);
        float ux = nx * inv, uy = ny * inv, uz = nz * inv;
        float d = ax * ux + ay * uy + az * uz;
        g_plane[f] = make_float4(ux, uy, uz, -d);
    } else {
        g_plane[f] = make_float4(0.0f, 0.0f, 0.0f, 0.0f);  // never culled
    }
}

// Evaluate one triangle exactly (bit-identical to reference); update lane best.
// Returns true if this lane's best improved.
__device__ __forceinline__ bool eval_tri(
    int fe, float px, float py, float pz,
    unsigned long long& best_key, float& best_sd)
{
    const float4* tq = reinterpret_cast<const float4*>(&g_tri[fe * 12]);
    float4 q0 = __ldg(&tq[0]);
    float4 q1 = __ldg(&tq[1]);
    float4 q2 = __ldg(&tq[2]);
    float ax = q0.x, ay = q0.y, az = q0.z;
    float bx = q0.w, by = q1.x, bz = q1.y;
    float cx = q1.z, cy = q1.w, cz = q2.x;
    float nx = q2.y, ny = q2.z, nz = q2.w;

    float abx = __fsub_rn(bx, ax), aby = __fsub_rn(by, ay), abz = __fsub_rn(bz, az);
    float acx = __fsub_rn(cx, ax), acy = __fsub_rn(cy, ay), acz = __fsub_rn(cz, az);
    float apx = __fsub_rn(px, ax), apy = __fsub_rn(py, ay), apz = __fsub_rn(pz, az);
    float bpx = __fsub_rn(px, bx), bpy = __fsub_rn(py, by), bpz = __fsub_rn(pz, bz);
    float cpx = __fsub_rn(px, cx), cpy = __fsub_rn(py, cy), cpz = __fsub_rn(pz, cz);

    float d1 = dot3(abx, aby, abz, apx, apy, apz);
    float d2 = dot3(acx, acy, acz, apx, apy, apz);
    float d3 = dot3(abx, aby, abz, bpx, bpy, bpz);
    float d4 = dot3(acx, acy, acz, bpx, bpy, bpz);
    float d5 = dot3(abx, aby, abz, cpx, cpy, cpz);
    float d6 = dot3(acx, acy, acz, cpx, cpy, cpz);

    float va = __fsub_rn(__fmul_rn(d3, d6), __fmul_rn(d5, d4));
    float vb = __fsub_rn(__fmul_rn(d5, d2), __fmul_rn(d1, d6));
    float vc = __fsub_rn(__fmul_rn(d1, d4), __fmul_rn(d3, d2));
    float denom = __fadd_rn(__fadd_rn(va, vb), vc);
    float v = sdiv(vb, denom);
    float w = sdiv(vc, denom);

    float e43 = __fsub_rn(d4, d3);
    float e56 = __fsub_rn(d5, d6);
    float t_bc = sdiv(e43, __fadd_rn(e43, e56));
    if (va <= 0.0f && e43 >= 0.0f && e56 >= 0.0f) {
        v = __fsub_rn(1.0f, t_bc); w = t_bc;
    }
    float t_ac = sdiv(d2, __fsub_rn(d2, d6));
    if (vb <= 0.0f && d2 >= 0.0f && d6 <= 0.0f) { v = 0.0f; w = t_ac; }
    float t_ab = sdiv(d1, __fsub_rn(d1, d3));
    if (vc <= 0.0f && d1 >= 0.0f && d3 <= 0.0f) { v = t_ab; w = 0.0f; }
    if (d6 >= 0.0f && d5 <= d6) { v = 0.0f; w = 1.0f; }
    if (d3 >= 0.0f && d4 <= d3) { v = 1.0f; w = 0.0f; }
    if (d1 <= 0.0f && d2 <= 0.0f) { v = 0.0f; w = 0.0f; }

    float clx = __fadd_rn(__fadd_rn(ax, __fmul_rn(v, abx)), __fmul_rn(w, acx));
    float cly = __fadd_rn(__fadd_rn(ay, __fmul_rn(v, aby)), __fmul_rn(w, acy));
    float clz = __fadd_rn(__fadd_rn(az, __fmul_rn(v, abz)), __fmul_rn(w, acz));
    float dx = __fsub_rn(px, clx);
    float dy = __fsub_rn(py, cly);
    float dz = __fsub_rn(pz, clz);
    float dist2 = dot3(dx, dy, dz, dx, dy, dz);

    unsigned long long key =
        ((unsigned long long)__float_as_uint(dist2) << 32) | (unsigned)fe;
    if (key < best_key) {
        best_key = key;
        best_sd = dot3(dx, dy, dz, nx, ny, nz);
        return true;
    }
    return false;
}

// ---------- kernel 2: warp-per-point, 4-wide plane cull + prefetch ----------
__global__ void __launch_bounds__(TPB) sdf_main(const float* __restrict__ points,
                                                float* __restrict__ out) {
    __shared__ int queue[WPB][QCAP];

    int warp_in_blk = threadIdx.x / 32;
    int lane = threadIdx.x % 32;
    int pid = blockIdx.x * WPB + warp_in_blk;

    float px = points[pid * 3 + 0];
    float py = points[pid * 3 + 1];
    float pz = points[pid * 3 + 2];

    // Seed upper bound from 1024 vertex-a distances
    float ub2 = CUDART_INF_F;
    #pragma unroll 4
    for (int i = 0; i < 32; i++) {
        int f = i * 32 + lane;
        const float4* tq = reinterpret_cast<const float4*>(&g_tri[f * 12]);
        float4 q0 = __ldg(&tq[0]);
        float dx = px - q0.x, dy = py - q0.y, dz = pz - q0.z;
        ub2 = fminf(ub2, fmaf(dx, dx, fmaf(dy, dy, dz * dz)));
    }
    #pragma unroll
    for (int o = 16; o > 0; o >>= 1)
        ub2 = fminf(ub2, __shfl_xor_sync(0xFFFFFFFFu, ub2, o));
    float sq = fmaf(sqrtf(ub2), 1.001f, 1e-6f);  // inflated upper bound on min dist

    unsigned long long best_key = 0xFFFFFFFFFFFFFFFFull;
    float best_sd = 0.0f;

    int qn = 0, qhead = 0;
    unsigned lanemask = (1u << lane) - 1u;

    // Prime the prefetch pipeline
    float4 pl0 = __ldg(&g_plane[lane]);
    float4 pl1 = __ldg(&g_plane[lane + 32]);
    float4 pl2 = __ldg(&g_plane[lane + 64]);
    float4 pl3 = __ldg(&g_plane[lane + 96]);

    for (int chunk = 0; chunk < NF; chunk += 128) {
        float pd0 = fabsf(fmaf(px, pl0.x, fmaf(py, pl0.y, fmaf(pz, pl0.z, pl0.w))));
        float pd1 = fabsf(fmaf(px, pl1.x, fmaf(py, pl1.y, fmaf(pz, pl1.z, pl1.w))));
        float pd2 = fabsf(fmaf(px, pl2.x, fmaf(py, pl2.y, fmaf(pz, pl2.z, pl2.w))));
        float pd3 = fabsf(fmaf(px, pl3.x, fmaf(py, pl3.y, fmaf(pz, pl3.z, pl3.w))));
        bool k0 = (pd0 <= sq);
        bool k1 = (pd1 <= sq);
        bool k2 = (pd2 <= sq);
        bool k3 = (pd3 <= sq);
        unsigned m0 = __ballot_sync(0xFFFFFFFFu, k0);
        unsigned m1 = __ballot_sync(0xFFFFFFFFu, k1);
        unsigned m2 = __ballot_sync(0xFFFFFFFFu, k2);
        unsigned m3 = __ballot_sync(0xFFFFFFFFu, k3);
        int n0 = __popc(m0);
        int n1 = __popc(m1);
        int n2 = __popc(m2);
        int n3 = __popc(m3);
        if (k0) queue[warp_in_blk][(qhead + qn + __popc(m0 & lanemask)) & (QCAP - 1)] = chunk + lane;
        if (k1) queue[warp_in_blk][(qhead + qn + n0 + __popc(m1 & lanemask)) & (QCAP - 1)] = chunk + lane + 32;
        if (k2) queue[warp_in_blk][(qhead + qn + n0 + n1 + __popc(m2 & lanemask)) & (QCAP - 1)] = chunk + lane + 64;
        if (k3) queue[warp_in_blk][(qhead + qn + n0 + n1 + n2 + __popc(m3 & lanemask)) & (QCAP - 1)] = chunk + lane + 96;
        qn += n0 + n1 + n2 + n3;

        // Prefetch next chunk's planes (overlaps with drain below)
        int nxt = chunk + 128;
        if (nxt < NF) {
            pl0 = __ldg(&g_plane[nxt + lane]);
            pl1 = __ldg(&g_plane[nxt + lane + 32]);
            pl2 = __ldg(&g_plane[nxt + lane + 64]);
            pl3 = __ldg(&g_plane[nxt + lane + 96]);
        }
        __syncwarp();

        while (qn >= 32) {
            int fe = queue[warp_in_blk][(qhead + lane) & (QCAP - 1)];
            qhead += 32;
            qn -= 32;
            bool improved = eval_tri(fe, px, py, pz, best_key, best_sd);
            if (__ballot_sync(0xFFFFFFFFu, improved)) {
                float bd2 = __uint_as_float((unsigned)(best_key >> 32));
                #pragma unroll
                for (int o = 16; o > 0; o >>= 1)
                    bd2 = fminf(bd2, __shfl_xor_sync(0xFFFFFFFFu, bd2, o));
                sq = fminf(sq, fmaf(sqrtf(bd2), 1.001f, 1e-6f));
            }
        }
        __syncwarp();
    }

    // Drain remaining queued survivors
    if (lane < qn) {
        int fe = queue[warp_in_blk][(qhead + lane) & (QCAP - 1)];
        eval_tri(fe, px, py, pz, best_key, best_sd);
    }
    __syncwarp();

    // Warp-reduce (key, sd) lexicographic min — matches argmin first-index tie-break
    #pragma unroll
    for (int o = 16; o > 0; o >>= 1) {
        unsigned long long ok = __shfl_xor_sync(0xFFFFFFFFu, best_key, o);
        float osd = __shfl_xor_sync(0xFFFFFFFFu, best_sd, o);
        if (ok < best_key) { best_key = ok; best_sd = osd; }
    }

    if (lane == 0) {
        float dist2 = __uint_as_float((unsigned)(best_key >> 32));
        float dist = sqrtf(fmaxf(dist2, 1e-12f));
        out[pid] = (best_sd > 0.0f) ? -dist : dist;
    }
}

extern "C" void kernel_launch(void* const* d_in, const int* in_sizes, int n_in,
                              void* d_out, int out_size) {
    const float* points   = (const float*)d_in[0];
    const float* vertices = (const float*)d_in[1];
    const int*   faces    = (const int*)d_in[2];
    float* out = (float*)d_out;

    precompute_tris<<<(NF + 255) / 256, 256>>>(vertices, faces);
    sdf_main<<<NP / WPB, TPB>>>(points, out);
}